// round 8
// baseline (speedup 1.0000x reference)
#include <cuda_runtime.h>
#include <cuda_fp16.h>
#include <cstdint>

#define HW_ 262144            // 512*512

// Fragment-linear fp16 weight images for mma.sync m16n8k16 B operand.
__device__ __align__(16) __half g_bf[3][65536];  // W1..W3 [kb(16)][n8pair(16)][lane(32)][8]
__device__ __align__(16) __half g_w0f[4096];     // W0 [1 kb][n8pair(16)][lane(32)][8], k<3 live
__device__ __align__(16) __half g_w4f[2048];     // W4 [kb(16)][lane(32)][2 k-halves x f16x2]
// Fragment-ordered bias packs: float4 {b[c], b[c+1], b[c+8], b[c+9]}, c = jj*16+tg*2
__device__ __align__(16) float4 g_c0f[64];       // layer0: b0 + style . W0[3:6]
__device__ __align__(16) float4 g_bsf[192];      // [l(3)][jj(16)][tg(4)]
__device__ float g_b4f[8];                       // b4 padded with zeros to 8 cols

// ---------------- prep: fp32 W -> fp16 fragment-linear + packed biases ----------------
__global__ void prep_kernel(const float* __restrict__ W0, const float* __restrict__ W1,
                            const float* __restrict__ W2, const float* __restrict__ W3,
                            const float* __restrict__ W4, const float* __restrict__ style,
                            const float* __restrict__ b0, const float* __restrict__ b1,
                            const float* __restrict__ b2, const float* __restrict__ b3,
                            const float* __restrict__ b4) {
  int t = blockIdx.x * blockDim.x + threadIdx.x;
  if (t < 196608) {
    int l = t >> 16, e = t & 65535;
    int k = e >> 8, n = e & 255;
    const float* W = (l == 0) ? W1 : (l == 1 ? W2 : W3);
    int kb = k >> 4, kr = k & 15;
    int n8 = n >> 3, g = n & 7;
    int tg = (kr >> 1) & 3;
    int lane = g * 4 + tg;
    int breg = kr >> 3, hs = kr & 1;
    int halfidx = (n8 & 1) * 4 + breg * 2 + hs;
    int dst = ((kb * 16 + (n8 >> 1)) * 32 + lane) * 8 + halfidx;
    g_bf[l][dst] = __float2half_rn(W[k * 256 + n]);
  } else if (t < 200704) {
    int e = t - 196608;                  // k(16) x n(256)
    int k = e >> 8, n = e & 255;
    int n8 = n >> 3, g = n & 7;
    int tg = (k >> 1) & 3;
    int lane = g * 4 + tg;
    int breg = k >> 3, hs = k & 1;
    int halfidx = (n8 & 1) * 4 + breg * 2 + hs;
    int dst = ((n8 >> 1) * 32 + lane) * 8 + halfidx;
    g_w0f[dst] = __float2half_rn(k < 3 ? W0[k * 256 + n] : 0.f);
  } else if (t < 202752) {
    int e = t - 200704;                  // kglob(256) x n(8)
    int kglob = e >> 3, n = e & 7;
    int kbG = kglob >> 4, kr = kglob & 15;
    int tg = (kr >> 1) & 3;
    int lane = n * 4 + tg;
    int breg = kr >> 3, hs = kr & 1;
    int dst = ((kbG * 32 + lane) * 2 + breg) * 2 + hs;
    g_w4f[dst] = __float2half_rn(n < 3 ? W4[kglob * 3 + n] : 0.f);
  } else if (t < 202816) {
    int e = t - 202752;                  // layer0 bias frag: jj(16) tg(4)
    int jj = e >> 2, tg = e & 3;
    int c = jj * 16 + tg * 2;
    float s0 = style[0], s1 = style[1], s2 = style[2];
    float4 v;
    v.x = b0[c]     + s0 * W0[768 + c]     + s1 * W0[1024 + c]     + s2 * W0[1280 + c];
    v.y = b0[c + 1] + s0 * W0[768 + c + 1] + s1 * W0[1024 + c + 1] + s2 * W0[1280 + c + 1];
    v.z = b0[c + 8] + s0 * W0[768 + c + 8] + s1 * W0[1024 + c + 8] + s2 * W0[1280 + c + 8];
    v.w = b0[c + 9] + s0 * W0[768 + c + 9] + s1 * W0[1024 + c + 9] + s2 * W0[1280 + c + 9];
    g_c0f[e] = v;
  } else if (t < 203008) {
    int e = t - 202816;                  // hidden bias frag: l(3) jj(16) tg(4)
    int l = e >> 6, r = e & 63;
    int jj = r >> 2, tg = r & 3;
    int c = jj * 16 + tg * 2;
    const float* B = (l == 0) ? b1 : (l == 1 ? b2 : b3);
    g_bsf[e] = make_float4(B[c], B[c + 1], B[c + 8], B[c + 9]);
  } else if (t < 203016) {
    int e = t - 203008;
    g_b4f[e] = (e < 3) ? b4[e] : 0.f;
  }
}

// ---------------- helpers ----------------
__device__ __forceinline__ uint32_t packh2(float lo, float hi) {
  uint32_t r;
  asm("cvt.rn.f16x2.f32 %0, %1, %2;" : "=f"(*(float*)&r) : "f"(hi), "f"(lo));
  return r;
}
__device__ __forceinline__ uint32_t tanh2(uint32_t p) {
  uint32_t r;
  asm("tanh.approx.f16x2 %0, %1;" : "=r"(r) : "r"(p));
  return r;
}
__device__ __forceinline__ uint32_t max0h2(uint32_t p) {
  uint32_t r;
  asm("max.f16x2 %0, %1, %2;" : "=r"(r) : "r"(p), "r"(0u));
  return r;
}
__device__ __forceinline__ void mma16816(float* c, const uint4& a, uint32_t b0, uint32_t b1) {
  asm volatile("mma.sync.aligned.m16n8k16.row.col.f32.f16.f16.f32 "
               "{%0,%1,%2,%3}, {%4,%5,%6,%7}, {%8,%9}, {%0,%1,%2,%3};"
               : "+f"(c[0]), "+f"(c[1]), "+f"(c[2]), "+f"(c[3])
               : "r"(a.x), "r"(a.y), "r"(a.z), "r"(a.w), "r"(b0), "r"(b1));
}

// ---------------- main kernel: fully register-resident, 16 pixels per warp ----------------
__global__ void __launch_bounds__(128, 2) cnilut_main(
    const float* __restrict__ x, float* __restrict__ out) {
  int tid = threadIdx.x, wid = tid >> 5, lane = tid & 31;
  int g = lane >> 2, tg = lane & 3;

  int wglob = blockIdx.x * 4 + wid;      // warp's 16 pixels: wglob*16 .. +15
  int p0 = wglob * 16;
  int img = p0 >> 18;
  int hw0 = p0 & (HW_ - 1);
  const float* xb = x + (size_t)img * 3 * HW_ + hw0;

  // x values this thread needs: channels tg*2, tg*2+1 at rows g and g+8
  float x00 = 0.f, x01 = 0.f, x10 = 0.f, x11 = 0.f;
  if (tg == 0) {
    x00 = xb[g];                          x01 = xb[HW_ + g];
    x10 = xb[g + 8];                      x11 = xb[HW_ + g + 8];
  } else if (tg == 1) {
    x00 = xb[2 * (size_t)HW_ + g];        x10 = xb[2 * (size_t)HW_ + g + 8];
  }
  // layer0 A fragment (k = tg*2, tg*2+1 live for k<3; k+8 all zero)
  uint4 af0 = make_uint4(packh2(x00, x01), packh2(x10, x11), 0u, 0u);

  float acc[16][2][4];
  uint4 afrag[16];

  // ---- layer 0: relu(x.W0 + c0) ----
  #pragma unroll
  for (int jj = 0; jj < 16; jj++) {
    float4 bv = __ldg(&g_c0f[jj * 4 + tg]);
    acc[jj][0][0] = bv.x; acc[jj][0][1] = bv.y; acc[jj][0][2] = bv.x; acc[jj][0][3] = bv.y;
    acc[jj][1][0] = bv.z; acc[jj][1][1] = bv.w; acc[jj][1][2] = bv.z; acc[jj][1][3] = bv.w;
  }
  #pragma unroll
  for (int j = 0; j < 16; j++) {
    uint4 bw = __ldg((const uint4*)g_w0f + j * 32 + lane);
    mma16816(acc[j][0], af0, bw.x, bw.y);
    mma16816(acc[j][1], af0, bw.z, bw.w);
  }
  #pragma unroll
  for (int jj = 0; jj < 16; jj++) {
    float* e = acc[jj][0];
    float* o = acc[jj][1];
    afrag[jj] = make_uint4(max0h2(packh2(e[0], e[1])), max0h2(packh2(e[2], e[3])),
                           max0h2(packh2(o[0], o[1])), max0h2(packh2(o[2], o[3])));
  }

  // ---- 3 hidden layers, no barriers; l==2 fuses the final 256->3 GEMM ----
  float res[4];
  res[0] = __ldg(&g_b4f[tg * 2]);     res[1] = __ldg(&g_b4f[tg * 2 + 1]);
  res[2] = res[0];                    res[3] = res[1];

  #pragma unroll 1
  for (int l = 0; l < 3; l++) {
    #pragma unroll
    for (int jj = 0; jj < 16; jj++) {
      float4 bv = __ldg(&g_bsf[l * 64 + jj * 4 + tg]);
      acc[jj][0][0] = bv.x; acc[jj][0][1] = bv.y; acc[jj][0][2] = bv.x; acc[jj][0][3] = bv.y;
      acc[jj][1][0] = bv.z; acc[jj][1][1] = bv.w; acc[jj][1][2] = bv.z; acc[jj][1][3] = bv.w;
    }

    const uint4* gB = (const uint4*)g_bf[l];
    #pragma unroll
    for (int kb = 0; kb < 16; kb++) {
      uint4 bf[8];
      #pragma unroll
      for (int p = 0; p < 8; p++) bf[p] = __ldg(gB + (kb * 16 + p) * 32 + lane);
      #pragma unroll
      for (int p = 0; p < 8; p++) {
        mma16816(acc[p][0], afrag[kb], bf[p].x, bf[p].y);
        mma16816(acc[p][1], afrag[kb], bf[p].z, bf[p].w);
      }
      #pragma unroll
      for (int p = 0; p < 8; p++) bf[p] = __ldg(gB + (kb * 16 + 8 + p) * 32 + lane);
      #pragma unroll
      for (int p = 0; p < 8; p++) {
        mma16816(acc[8 + p][0], afrag[kb], bf[p].x, bf[p].y);
        mma16816(acc[8 + p][1], afrag[kb], bf[p].z, bf[p].w);
      }
    }

    if (l < 2) {
      // epilogue: tanh -> next layer's A fragments (register-local remap)
      #pragma unroll
      for (int jj = 0; jj < 16; jj++) {
        float* e = acc[jj][0];
        float* o = acc[jj][1];
        afrag[jj] = make_uint4(tanh2(packh2(e[0], e[1])), tanh2(packh2(e[2], e[3])),
                               tanh2(packh2(o[0], o[1])), tanh2(packh2(o[2], o[3])));
      }
    } else {
      // fused final: tanh-pack each k-fragment, immediately MMA into res (N=8, 3 live)
      #pragma unroll
      for (int kb = 0; kb < 16; kb++) {
        uint2 wv = __ldg((const uint2*)g_w4f + kb * 32 + lane);
        float* e = acc[kb][0];
        float* o = acc[kb][1];
        uint4 frag;
        frag.x = tanh2(packh2(e[0], e[1]));
        frag.y = tanh2(packh2(e[2], e[3]));
        frag.z = tanh2(packh2(o[0], o[1]));
        frag.w = tanh2(packh2(o[2], o[3]));
        mma16816(res, frag, wv.x, wv.y);
      }
    }
  }

  // ---- residual + clip + store (res rows g,g+8 x cols tg*2,tg*2+1; b4 already in res) ----
  float* ob = out + (size_t)img * 3 * HW_ + hw0;
  if (tg == 0) {
    ob[g]            = fminf(fmaxf(x00 + res[0], 0.f), 1.f);
    ob[HW_ + g]      = fminf(fmaxf(x01 + res[1], 0.f), 1.f);
    ob[g + 8]        = fminf(fmaxf(x10 + res[2], 0.f), 1.f);
    ob[HW_ + g + 8]  = fminf(fmaxf(x11 + res[3], 0.f), 1.f);
  } else if (tg == 1) {
    ob[2 * (size_t)HW_ + g]     = fminf(fmaxf(x00 + res[0], 0.f), 1.f);
    ob[2 * (size_t)HW_ + g + 8] = fminf(fmaxf(x10 + res[2], 0.f), 1.f);
  }
}

extern "C" void kernel_launch(void* const* d_in, const int* in_sizes, int n_in,
                              void* d_out, int out_size) {
  const float* x     = (const float*)d_in[0];
  const float* style = (const float*)d_in[1];
  const float* W0    = (const float*)d_in[2];
  const float* b0    = (const float*)d_in[3];
  const float* W1    = (const float*)d_in[4];
  const float* b1    = (const float*)d_in[5];
  const float* W2    = (const float*)d_in[6];
  const float* b2    = (const float*)d_in[7];
  const float* W3    = (const float*)d_in[8];
  const float* b3    = (const float*)d_in[9];
  const float* W4    = (const float*)d_in[10];
  const float* b4    = (const float*)d_in[11];
  float* out = (float*)d_out;

  prep_kernel<<<794, 256>>>(W0, W1, W2, W3, W4, style, b0, b1, b2, b3, b4);
  cnilut_main<<<16384, 128>>>(x, out);
}

// round 10
// speedup vs baseline: 1.2341x; 1.2341x over previous
#include <cuda_runtime.h>
#include <cuda_fp16.h>
#include <cstdint>

#define HW_ 262144            // 512*512
#define NPAIRS 8192           // pairs of 64-px tiles
#define GRIDP 152

// Fragment-linear fp16 weight images for mma.sync m16n8k16 B operand.
__device__ __align__(16) __half g_bf[3][65536];  // W1..W3 [kb(16)][n8pair(16)][lane(32)][8]
__device__ __align__(16) __half g_w0f[4096];     // W0 [1 kb][n8pair(16)][lane(32)][8], k<3 live
__device__ __align__(16) __half g_w4f[2048];     // W4 [kb(16)][lane(32)][2 x f16x2]
__device__ __align__(16) float4 g_c0f[64];       // layer0 bias frags [pair(16)][tg(4)]
__device__ __align__(16) float4 g_bsf[192];      // [l(3)][pair(16)][tg(4)]
__device__ float g_b4f[8];

// ---------------- prep ----------------
__global__ void prep_kernel(const float* __restrict__ W0, const float* __restrict__ W1,
                            const float* __restrict__ W2, const float* __restrict__ W3,
                            const float* __restrict__ W4, const float* __restrict__ style,
                            const float* __restrict__ b0, const float* __restrict__ b1,
                            const float* __restrict__ b2, const float* __restrict__ b3,
                            const float* __restrict__ b4) {
  int t = blockIdx.x * blockDim.x + threadIdx.x;
  if (t < 196608) {
    int l = t >> 16, e = t & 65535;
    int k = e >> 8, n = e & 255;
    const float* W = (l == 0) ? W1 : (l == 1 ? W2 : W3);
    int kb = k >> 4, kr = k & 15;
    int n8 = n >> 3, g = n & 7;
    int tg = (kr >> 1) & 3;
    int lane = g * 4 + tg;
    int breg = kr >> 3, hs = kr & 1;
    int halfidx = (n8 & 1) * 4 + breg * 2 + hs;
    int dst = ((kb * 16 + (n8 >> 1)) * 32 + lane) * 8 + halfidx;
    g_bf[l][dst] = __float2half_rn(W[k * 256 + n]);
  } else if (t < 200704) {
    int e = t - 196608;
    int k = e >> 8, n = e & 255;
    int n8 = n >> 3, g = n & 7;
    int tg = (k >> 1) & 3;
    int lane = g * 4 + tg;
    int breg = k >> 3, hs = k & 1;
    int halfidx = (n8 & 1) * 4 + breg * 2 + hs;
    int dst = ((n8 >> 1) * 32 + lane) * 8 + halfidx;
    g_w0f[dst] = __float2half_rn(k < 3 ? W0[k * 256 + n] : 0.f);
  } else if (t < 202752) {
    int e = t - 200704;
    int kglob = e >> 3, n = e & 7;
    int kbG = kglob >> 4, kr = kglob & 15;
    int tg = (kr >> 1) & 3;
    int lane = n * 4 + tg;
    int breg = kr >> 3, hs = kr & 1;
    int dst = ((kbG * 32 + lane) * 2 + breg) * 2 + hs;
    g_w4f[dst] = __float2half_rn(n < 3 ? W4[kglob * 3 + n] : 0.f);
  } else if (t < 202816) {
    int e = t - 202752;
    int jj = e >> 2, tg = e & 3;
    int c = jj * 16 + tg * 2;
    float s0 = style[0], s1 = style[1], s2 = style[2];
    float4 v;
    v.x = b0[c]     + s0 * W0[768 + c]     + s1 * W0[1024 + c]     + s2 * W0[1280 + c];
    v.y = b0[c + 1] + s0 * W0[768 + c + 1] + s1 * W0[1024 + c + 1] + s2 * W0[1280 + c + 1];
    v.z = b0[c + 8] + s0 * W0[768 + c + 8] + s1 * W0[1024 + c + 8] + s2 * W0[1280 + c + 8];
    v.w = b0[c + 9] + s0 * W0[768 + c + 9] + s1 * W0[1024 + c + 9] + s2 * W0[1280 + c + 9];
    g_c0f[e] = v;
  } else if (t < 203008) {
    int e = t - 202816;
    int l = e >> 6, r = e & 63;
    int jj = r >> 2, tg = r & 3;
    int c = jj * 16 + tg * 2;
    const float* B = (l == 0) ? b1 : (l == 1 ? b2 : b3);
    g_bsf[e] = make_float4(B[c], B[c + 1], B[c + 8], B[c + 9]);
  } else if (t < 203016) {
    int e = t - 203008;
    g_b4f[e] = (e < 3) ? b4[e] : 0.f;
  }
}

// ---------------- helpers ----------------
__device__ __forceinline__ uint32_t packh2(float lo, float hi) {
  uint32_t r;
  asm("cvt.rn.f16x2.f32 %0, %1, %2;" : "=f"(*(float*)&r) : "f"(hi), "f"(lo));
  return r;
}
__device__ __forceinline__ uint32_t tanh2(uint32_t p) {
  uint32_t r;
  asm("tanh.approx.f16x2 %0, %1;" : "=r"(r) : "r"(p));
  return r;
}
__device__ __forceinline__ uint32_t max0h2(uint32_t p) {
  uint32_t r;
  asm("max.f16x2 %0, %1, %2;" : "=r"(r) : "r"(p), "r"(0u));
  return r;
}
__device__ __forceinline__ void mma16816(float* c, const uint4& a, uint32_t b0, uint32_t b1) {
  asm volatile("mma.sync.aligned.m16n8k16.row.col.f32.f16.f16.f32 "
               "{%0,%1,%2,%3}, {%4,%5,%6,%7}, {%8,%9}, {%0,%1,%2,%3};"
               : "+f"(c[0]), "+f"(c[1]), "+f"(c[2]), "+f"(c[3])
               : "r"(a.x), "r"(a.y), "r"(a.z), "r"(a.w), "r"(b0), "r"(b1));
}
__device__ __forceinline__ float clipf(float v) { return fminf(fmaxf(v, 0.f), 1.f); }

__device__ __forceinline__ void bias_from(float acc[4][4][4], const float4* src, int wid, int tg) {
  #pragma unroll
  for (int jp = 0; jp < 2; jp++) {
    float4 bv = __ldg(&src[(wid * 2 + jp) * 4 + tg]);
    #pragma unroll
    for (int i = 0; i < 4; i++) {
      acc[i][2 * jp][0] = bv.x; acc[i][2 * jp][1] = bv.y;
      acc[i][2 * jp][2] = bv.x; acc[i][2 * jp][3] = bv.y;
      acc[i][2 * jp + 1][0] = bv.z; acc[i][2 * jp + 1][1] = bv.w;
      acc[i][2 * jp + 1][2] = bv.z; acc[i][2 * jp + 1][3] = bv.w;
    }
  }
}
__device__ __forceinline__ void l0_mma(float acc[4][4][4], const uint4* af0, int wid, int lane) {
  #pragma unroll
  for (int jp = 0; jp < 2; jp++) {
    uint4 bw = __ldg((const uint4*)g_w0f + (wid * 2 + jp) * 32 + lane);
    #pragma unroll
    for (int i = 0; i < 4; i++) {
      mma16816(acc[i][2 * jp],     af0[i], bw.x, bw.y);
      mma16816(acc[i][2 * jp + 1], af0[i], bw.z, bw.w);
    }
  }
}
// make frag (i, jp) from acc; SINK 0=relu, 1=tanh
template<int SINK>
__device__ __forceinline__ uint4 make_frag(float acc[4][4][4], int i, int jp) {
  float* e = acc[i][2 * jp];
  float* o = acc[i][2 * jp + 1];
  uint4 f;
  if (SINK == 0) {
    f.x = max0h2(packh2(e[0], e[1])); f.y = max0h2(packh2(e[2], e[3]));
    f.z = max0h2(packh2(o[0], o[1])); f.w = max0h2(packh2(o[2], o[3]));
  } else {
    f.x = tanh2(packh2(e[0], e[1])); f.y = tanh2(packh2(e[2], e[3]));
    f.z = tanh2(packh2(o[0], o[1])); f.w = tanh2(packh2(o[2], o[3]));
  }
  return f;
}
// Phase: S1 = MMA of one layer (reads Ard, acc pre-bias'd); S2 = frag production.
// SINK: 0 relu->STS, 1 tanh->STS, 2 tanh->final MMA into res
template<int SINK>
__device__ __forceinline__ void phase(float accS1[4][4][4], const uint4* __restrict__ Ard,
                                      const __half* __restrict__ gBl,
                                      float accS2[4][4][4], uint4* __restrict__ Awr,
                                      float res[4][4], int wid, int lane, int tg) {
  const uint4* gB = (const uint4*)gBl;
  uint4 bf[2][2];
  #pragma unroll
  for (int jp = 0; jp < 2; jp++) bf[0][jp] = __ldg(gB + (wid * 2 + jp) * 32 + lane);
  #pragma unroll
  for (int kb = 0; kb < 16; kb++) {
    int cur = kb & 1, nxt = cur ^ 1;
    if (kb < 15) {
      #pragma unroll
      for (int jp = 0; jp < 2; jp++)
        bf[nxt][jp] = __ldg(gB + ((kb + 1) * 16 + wid * 2 + jp) * 32 + lane);
    }
    uint4 af[4];
    #pragma unroll
    for (int i = 0; i < 4; i++) af[i] = Ard[(i * 16 + kb) * 32 + lane];
    #pragma unroll
    for (int i = 0; i < 4; i++)
      #pragma unroll
      for (int jp = 0; jp < 2; jp++) {
        mma16816(accS1[i][2 * jp],     af[i], bf[cur][jp].x, bf[cur][jp].y);
        mma16816(accS1[i][2 * jp + 1], af[i], bf[cur][jp].z, bf[cur][jp].w);
      }
    if (kb & 1) {   // one S2 frag per 2 kb: 8 total
      int ei = kb >> 1, i = ei >> 1, jp = ei & 1;
      uint4 f = make_frag<(SINK == 0 ? 0 : 1)>(accS2, i, jp);
      if (SINK == 2) {
        uint2 wv = __ldg((const uint2*)g_w4f + (wid * 2 + jp) * 32 + lane);
        mma16816(res[i], f, wv.x, wv.y);
      } else {
        Awr[(i * 16 + (wid * 2 + jp)) * 32 + lane] = f;
      }
    }
  }
}
template<int SINK>
__device__ __forceinline__ void epi_standalone(float acc[4][4][4], uint4* Awr,
                                               float res[4][4], int wid, int lane) {
  #pragma unroll
  for (int ei = 0; ei < 8; ei++) {
    int i = ei >> 1, jp = ei & 1;
    uint4 f = make_frag<(SINK == 0 ? 0 : 1)>(acc, i, jp);
    if (SINK == 2) {
      uint2 wv = __ldg((const uint2*)g_w4f + (wid * 2 + jp) * 32 + lane);
      mma16816(res[i], f, wv.x, wv.y);
    } else {
      Awr[(i * 16 + (wid * 2 + jp)) * 32 + lane] = f;
    }
  }
}
__device__ __forceinline__ void res_zero(float res[4][4]) {
  #pragma unroll
  for (int i = 0; i < 4; i++) { res[i][0] = 0.f; res[i][1] = 0.f; res[i][2] = 0.f; res[i][3] = 0.f; }
}
__device__ __forceinline__ void load_af0(uint4 af0[4], const float* __restrict__ x,
                                         int tile, int g, int tg) {
  #pragma unroll
  for (int i = 0; i < 4; i++) {
    uint32_t ax = 0, ay = 0;
    if (tg < 2) {
      int rp = tile * 64 + i * 16 + g;
      int im = rp >> 18, h = rp & (HW_ - 1);
      const float* xq = x + (size_t)im * 3 * HW_ + h;
      float va  = (tg == 0) ? __ldg(xq)            : __ldg(xq + 2 * (size_t)HW_);
      float vb  = (tg == 0) ? __ldg(xq + HW_)      : 0.f;
      float va2 = (tg == 0) ? __ldg(xq + 8)        : __ldg(xq + 2 * (size_t)HW_ + 8);
      float vb2 = (tg == 0) ? __ldg(xq + HW_ + 8)  : 0.f;
      ax = packh2(va, vb);
      ay = packh2(va2, vb2);
    }
    af0[i] = make_uint4(ax, ay, 0u, 0u);
  }
}
__device__ __forceinline__ void reduce_store(const float4* __restrict__ P, int tile,
                                             const float* __restrict__ x, float* __restrict__ out,
                                             int wid, int lane, int g, int tg) {
  float4 s = P[(wid * 8) * 32 + lane];
  #pragma unroll
  for (int k = 1; k < 8; k++) {
    float4 q = P[(wid * 8 + k) * 32 + lane];
    s.x += q.x; s.y += q.y; s.z += q.z; s.w += q.w;
  }
  int p = tile * 64 + wid * 16 + g;
  int img = p >> 18, hw = p & (HW_ - 1);
  const float* xb = x + (size_t)img * 3 * HW_ + hw;
  float* ob = out + (size_t)img * 3 * HW_ + hw;
  if (tg == 0) {
    float bb0 = __ldg(&g_b4f[0]), bb1 = __ldg(&g_b4f[1]);
    ob[0]       = clipf(__ldg(xb) + s.x + bb0);
    ob[HW_]     = clipf(__ldg(xb + HW_) + s.y + bb1);
    ob[8]       = clipf(__ldg(xb + 8) + s.z + bb0);
    ob[HW_ + 8] = clipf(__ldg(xb + HW_ + 8) + s.w + bb1);
  } else if (tg == 1) {
    float bb2 = __ldg(&g_b4f[2]);
    ob[2 * (size_t)HW_]     = clipf(__ldg(xb + 2 * (size_t)HW_) + s.x + bb2);
    ob[2 * (size_t)HW_ + 8] = clipf(__ldg(xb + 2 * (size_t)HW_ + 8) + s.z + bb2);
  }
}

// ---------------- main: persistent, dual-stream pipelined, 256 thr, 1 CTA/SM ----------------
#define SMEM_TOTAL 98304

__global__ void __launch_bounds__(256, 1) cnilut_main(
    const float* __restrict__ x, float* __restrict__ out) {
  extern __shared__ char smem[];
  uint4* B0 = (uint4*)smem;
  uint4* B1 = (uint4*)(smem + 32768);
  uint4* B2 = (uint4*)(smem + 65536);

  int tid = threadIdx.x, wid = tid >> 5, lane = tid & 31;
  int g = lane >> 2, tg = lane & 3;

  float accX[4][4][4], accY[4][4][4], resX[4][4], resY[4][4];
  uint4 af0X[4], af0Y[4];

  int pair0 = blockIdx.x;
  load_af0(af0X, x, 2 * pair0, g, tg);
  load_af0(af0Y, x, 2 * pair0 + 1, g, tg);

  #pragma unroll 1
  for (int pair = pair0; pair < NPAIRS; pair += GRIDP) {
    int tX = 2 * pair, tY = 2 * pair + 1;

    // ---- prologue: X.L0 -> B0; bias accY(c0) ----
    bias_from(accX, g_c0f, wid, tg);
    l0_mma(accX, af0X, wid, lane);
    epi_standalone<0>(accX, B0, nullptr, wid, lane);
    bias_from(accY, g_c0f, wid, tg);
    __syncthreads();

    // ---- P1: X.H1 (B0) || Y.L0 MMA + relu frags -> B1 ----
    bias_from(accX, g_bsf, wid, tg);
    l0_mma(accY, af0Y, wid, lane);
    phase<0>(accX, B0, g_bf[0], accY, B1, nullptr, wid, lane, tg);
    __syncthreads();

    // ---- P2: Y.H1 (B1) || X.H1-epi tanh -> B2 ----
    bias_from(accY, g_bsf, wid, tg);
    phase<1>(accY, B1, g_bf[0], accX, B2, nullptr, wid, lane, tg);
    __syncthreads();

    // ---- P3: X.H2 (B2) || Y.H1-epi tanh -> B0 ----
    bias_from(accX, g_bsf + 64, wid, tg);
    phase<1>(accX, B2, g_bf[1], accY, B0, nullptr, wid, lane, tg);
    __syncthreads();

    // ---- P4: Y.H2 (B0) || X.H2-epi tanh -> B1 ----
    bias_from(accY, g_bsf + 64, wid, tg);
    phase<1>(accY, B0, g_bf[1], accX, B1, nullptr, wid, lane, tg);
    __syncthreads();

    // ---- P5: X.H3 (B1) || Y.H2-epi tanh -> B2 ----
    bias_from(accX, g_bsf + 128, wid, tg);
    phase<1>(accX, B1, g_bf[2], accY, B2, nullptr, wid, lane, tg);
    __syncthreads();

    // ---- P6: Y.H3 (B2) || X.final (tanh + MMA into resX); partials -> B0 ----
    bias_from(accY, g_bsf + 128, wid, tg);
    res_zero(resX);
    phase<2>(accY, B2, g_bf[2], accX, nullptr, resX, wid, lane, tg);
    {
      float4* PX = (float4*)B0;
      #pragma unroll
      for (int i = 0; i < 4; i++)
        PX[(i * 8 + wid) * 32 + lane] = make_float4(resX[i][0], resX[i][1], resX[i][2], resX[i][3]);
    }
    __syncthreads();

    // ---- P7: Y.final standalone -> partials B1; X reduce+store; next-pair x prefetch ----
    if (pair + GRIDP < NPAIRS) {
      load_af0(af0X, x, 2 * (pair + GRIDP), g, tg);
      load_af0(af0Y, x, 2 * (pair + GRIDP) + 1, g, tg);
    }
    res_zero(resY);
    epi_standalone<2>(accY, nullptr, resY, wid, lane);
    {
      float4* PY = (float4*)B1;
      #pragma unroll
      for (int i = 0; i < 4; i++)
        PY[(i * 8 + wid) * 32 + lane] = make_float4(resY[i][0], resY[i][1], resY[i][2], resY[i][3]);
    }
    if (wid < 4) reduce_store((const float4*)B0, tX, x, out, wid, lane, g, tg);
    __syncthreads();

    // ---- P8: Y reduce+store ----
    if (wid < 4) reduce_store((const float4*)B1, tY, x, out, wid, lane, g, tg);
  }
}

extern "C" void kernel_launch(void* const* d_in, const int* in_sizes, int n_in,
                              void* d_out, int out_size) {
  const float* x     = (const float*)d_in[0];
  const float* style = (const float*)d_in[1];
  const float* W0    = (const float*)d_in[2];
  const float* b0    = (const float*)d_in[3];
  const float* W1    = (const float*)d_in[4];
  const float* b1    = (const float*)d_in[5];
  const float* W2    = (const float*)d_in[6];
  const float* b2    = (const float*)d_in[7];
  const float* W3    = (const float*)d_in[8];
  const float* b3    = (const float*)d_in[9];
  const float* W4    = (const float*)d_in[10];
  const float* b4    = (const float*)d_in[11];
  float* out = (float*)d_out;

  prep_kernel<<<794, 256>>>(W0, W1, W2, W3, W4, style, b0, b1, b2, b3, b4);
  cudaFuncSetAttribute(cnilut_main, cudaFuncAttributeMaxDynamicSharedMemorySize, SMEM_TOTAL);
  cnilut_main<<<GRIDP, 256, SMEM_TOTAL>>>(x, out);
}

// round 11
// speedup vs baseline: 1.2390x; 1.0040x over previous
#include <cuda_runtime.h>
#include <cuda_fp16.h>
#include <cstdint>

#define HW_ 262144            // 512*512
#define NPAIRS 8192           // pairs of 64-px tiles
#define GRIDP 152

// Fragment-linear fp16 weight images for mma.sync m16n8k16 B operand.
__device__ __align__(16) __half g_bf[3][65536];  // W1..W3 [kb(16)][n8pair(16)][lane(32)][8]
__device__ __align__(16) __half g_w0f[4096];     // W0 [1 kb][n8pair(16)][lane(32)][8], k<3 live
__device__ __align__(16) __half g_w4f[2048];     // W4 [kb(16)][lane(32)][2 x f16x2]
__device__ __align__(16) float4 g_c0f[64];       // layer0 bias frags [pair(16)][tg(4)]
__device__ __align__(16) float4 g_bsf[192];      // [l(3)][pair(16)][tg(4)]
__device__ float g_b4f[8];

// ---------------- prep ----------------
__global__ void prep_kernel(const float* __restrict__ W0, const float* __restrict__ W1,
                            const float* __restrict__ W2, const float* __restrict__ W3,
                            const float* __restrict__ W4, const float* __restrict__ style,
                            const float* __restrict__ b0, const float* __restrict__ b1,
                            const float* __restrict__ b2, const float* __restrict__ b3,
                            const float* __restrict__ b4) {
  int t = blockIdx.x * blockDim.x + threadIdx.x;
  if (t < 196608) {
    int l = t >> 16, e = t & 65535;
    int k = e >> 8, n = e & 255;
    const float* W = (l == 0) ? W1 : (l == 1 ? W2 : W3);
    int kb = k >> 4, kr = k & 15;
    int n8 = n >> 3, g = n & 7;
    int tg = (kr >> 1) & 3;
    int lane = g * 4 + tg;
    int breg = kr >> 3, hs = kr & 1;
    int halfidx = (n8 & 1) * 4 + breg * 2 + hs;
    int dst = ((kb * 16 + (n8 >> 1)) * 32 + lane) * 8 + halfidx;
    g_bf[l][dst] = __float2half_rn(W[k * 256 + n]);
  } else if (t < 200704) {
    int e = t - 196608;
    int k = e >> 8, n = e & 255;
    int n8 = n >> 3, g = n & 7;
    int tg = (k >> 1) & 3;
    int lane = g * 4 + tg;
    int breg = k >> 3, hs = k & 1;
    int halfidx = (n8 & 1) * 4 + breg * 2 + hs;
    int dst = ((n8 >> 1) * 32 + lane) * 8 + halfidx;
    g_w0f[dst] = __float2half_rn(k < 3 ? W0[k * 256 + n] : 0.f);
  } else if (t < 202752) {
    int e = t - 200704;
    int kglob = e >> 3, n = e & 7;
    int kbG = kglob >> 4, kr = kglob & 15;
    int tg = (kr >> 1) & 3;
    int lane = n * 4 + tg;
    int breg = kr >> 3, hs = kr & 1;
    int dst = ((kbG * 32 + lane) * 2 + breg) * 2 + hs;
    g_w4f[dst] = __float2half_rn(n < 3 ? W4[kglob * 3 + n] : 0.f);
  } else if (t < 202816) {
    int e = t - 202752;
    int jj = e >> 2, tg = e & 3;
    int c = jj * 16 + tg * 2;
    float s0 = style[0], s1 = style[1], s2 = style[2];
    float4 v;
    v.x = b0[c]     + s0 * W0[768 + c]     + s1 * W0[1024 + c]     + s2 * W0[1280 + c];
    v.y = b0[c + 1] + s0 * W0[768 + c + 1] + s1 * W0[1024 + c + 1] + s2 * W0[1280 + c + 1];
    v.z = b0[c + 8] + s0 * W0[768 + c + 8] + s1 * W0[1024 + c + 8] + s2 * W0[1280 + c + 8];
    v.w = b0[c + 9] + s0 * W0[768 + c + 9] + s1 * W0[1024 + c + 9] + s2 * W0[1280 + c + 9];
    g_c0f[e] = v;
  } else if (t < 203008) {
    int e = t - 202816;
    int l = e >> 6, r = e & 63;
    int jj = r >> 2, tg = r & 3;
    int c = jj * 16 + tg * 2;
    const float* B = (l == 0) ? b1 : (l == 1 ? b2 : b3);
    g_bsf[e] = make_float4(B[c], B[c + 1], B[c + 8], B[c + 9]);
  } else if (t < 203016) {
    int e = t - 203008;
    g_b4f[e] = (e < 3) ? b4[e] : 0.f;
  }
}

// ---------------- helpers ----------------
__device__ __forceinline__ uint32_t packh2(float lo, float hi) {
  uint32_t r;
  asm("cvt.rn.f16x2.f32 %0, %1, %2;" : "=f"(*(float*)&r) : "f"(hi), "f"(lo));
  return r;
}
__device__ __forceinline__ uint32_t tanh2(uint32_t p) {
  uint32_t r;
  asm("tanh.approx.f16x2 %0, %1;" : "=r"(r) : "r"(p));
  return r;
}
__device__ __forceinline__ uint32_t max0h2(uint32_t p) {
  uint32_t r;
  asm("max.f16x2 %0, %1, %2;" : "=r"(r) : "r"(p), "r"(0u));
  return r;
}
__device__ __forceinline__ void mma16816(float* c, const uint4& a, uint32_t b0, uint32_t b1) {
  asm volatile("mma.sync.aligned.m16n8k16.row.col.f32.f16.f16.f32 "
               "{%0,%1,%2,%3}, {%4,%5,%6,%7}, {%8,%9}, {%0,%1,%2,%3};"
               : "+f"(c[0]), "+f"(c[1]), "+f"(c[2]), "+f"(c[3])
               : "r"(a.x), "r"(a.y), "r"(a.z), "r"(a.w), "r"(b0), "r"(b1));
}
// A fragment with zero upper-k half (layer 0)
__device__ __forceinline__ void mma16816_a2(float* c, uint32_t ax, uint32_t ay,
                                            uint32_t b0, uint32_t b1) {
  asm volatile("mma.sync.aligned.m16n8k16.row.col.f32.f16.f16.f32 "
               "{%0,%1,%2,%3}, {%4,%5,%6,%7}, {%8,%9}, {%0,%1,%2,%3};"
               : "+f"(c[0]), "+f"(c[1]), "+f"(c[2]), "+f"(c[3])
               : "r"(ax), "r"(ay), "r"(0u), "r"(0u), "r"(b0), "r"(b1));
}
__device__ __forceinline__ float clipf(float v) { return fminf(fmaxf(v, 0.f), 1.f); }

__device__ __forceinline__ void bias_from(float acc[4][4][4], const float4* src, int wid, int tg) {
  #pragma unroll
  for (int jp = 0; jp < 2; jp++) {
    float4 bv = __ldg(&src[(wid * 2 + jp) * 4 + tg]);
    #pragma unroll
    for (int i = 0; i < 4; i++) {
      acc[i][2 * jp][0] = bv.x; acc[i][2 * jp][1] = bv.y;
      acc[i][2 * jp][2] = bv.x; acc[i][2 * jp][3] = bv.y;
      acc[i][2 * jp + 1][0] = bv.z; acc[i][2 * jp + 1][1] = bv.w;
      acc[i][2 * jp + 1][2] = bv.z; acc[i][2 * jp + 1][3] = bv.w;
    }
  }
}
__device__ __forceinline__ void l0_mma(float acc[4][4][4], const uint2* af0, int wid, int lane) {
  #pragma unroll
  for (int jp = 0; jp < 2; jp++) {
    uint4 bw = __ldg((const uint4*)g_w0f + (wid * 2 + jp) * 32 + lane);
    #pragma unroll
    for (int i = 0; i < 4; i++) {
      mma16816_a2(acc[i][2 * jp],     af0[i].x, af0[i].y, bw.x, bw.y);
      mma16816_a2(acc[i][2 * jp + 1], af0[i].x, af0[i].y, bw.z, bw.w);
    }
  }
}
// make frag (i, jp) from acc; SINK 0=relu, 1=tanh
template<int SINK>
__device__ __forceinline__ uint4 make_frag(float acc[4][4][4], int i, int jp) {
  float* e = acc[i][2 * jp];
  float* o = acc[i][2 * jp + 1];
  uint4 f;
  if (SINK == 0) {
    f.x = max0h2(packh2(e[0], e[1])); f.y = max0h2(packh2(e[2], e[3]));
    f.z = max0h2(packh2(o[0], o[1])); f.w = max0h2(packh2(o[2], o[3]));
  } else {
    f.x = tanh2(packh2(e[0], e[1])); f.y = tanh2(packh2(e[2], e[3]));
    f.z = tanh2(packh2(o[0], o[1])); f.w = tanh2(packh2(o[2], o[3]));
  }
  return f;
}
// Phase: S1 = MMA of one layer (reads Ard, acc pre-bias'd); S2 = frag production.
// SINK: 0 relu->STS, 1 tanh->STS, 2 tanh->final MMA into res
template<int SINK>
__device__ __forceinline__ void phase(float accS1[4][4][4], const uint4* __restrict__ Ard,
                                      const __half* __restrict__ gBl,
                                      float accS2[4][4][4], uint4* __restrict__ Awr,
                                      float res[4][4], int wid, int lane, int tg) {
  const uint4* gB = (const uint4*)gBl;
  uint4 bf[2][2];
  #pragma unroll
  for (int jp = 0; jp < 2; jp++) bf[0][jp] = __ldg(gB + (wid * 2 + jp) * 32 + lane);
  #pragma unroll
  for (int kb = 0; kb < 16; kb++) {
    int cur = kb & 1, nxt = cur ^ 1;
    if (kb < 15) {
      #pragma unroll
      for (int jp = 0; jp < 2; jp++)
        bf[nxt][jp] = __ldg(gB + ((kb + 1) * 16 + wid * 2 + jp) * 32 + lane);
    }
    uint4 af[4];
    #pragma unroll
    for (int i = 0; i < 4; i++) af[i] = Ard[(i * 16 + kb) * 32 + lane];
    #pragma unroll
    for (int i = 0; i < 4; i++)
      #pragma unroll
      for (int jp = 0; jp < 2; jp++) {
        mma16816(accS1[i][2 * jp],     af[i], bf[cur][jp].x, bf[cur][jp].y);
        mma16816(accS1[i][2 * jp + 1], af[i], bf[cur][jp].z, bf[cur][jp].w);
      }
    if (kb & 1) {   // one S2 frag per 2 kb: 8 total
      int ei = kb >> 1, i = ei >> 1, jp = ei & 1;
      uint4 f = make_frag<(SINK == 0 ? 0 : 1)>(accS2, i, jp);
      if (SINK == 2) {
        uint2 wv = __ldg((const uint2*)g_w4f + (wid * 2 + jp) * 32 + lane);
        mma16816(res[i], f, wv.x, wv.y);
      } else {
        Awr[(i * 16 + (wid * 2 + jp)) * 32 + lane] = f;
      }
    }
  }
}
template<int SINK>
__device__ __forceinline__ void epi_standalone(float acc[4][4][4], uint4* Awr,
                                               float res[4][4], int wid, int lane) {
  #pragma unroll
  for (int ei = 0; ei < 8; ei++) {
    int i = ei >> 1, jp = ei & 1;
    uint4 f = make_frag<(SINK == 0 ? 0 : 1)>(acc, i, jp);
    if (SINK == 2) {
      uint2 wv = __ldg((const uint2*)g_w4f + (wid * 2 + jp) * 32 + lane);
      mma16816(res[i], f, wv.x, wv.y);
    } else {
      Awr[(i * 16 + (wid * 2 + jp)) * 32 + lane] = f;
    }
  }
}
__device__ __forceinline__ void res_zero(float res[4][4]) {
  #pragma unroll
  for (int i = 0; i < 4; i++) { res[i][0] = 0.f; res[i][1] = 0.f; res[i][2] = 0.f; res[i][3] = 0.f; }
}
__device__ __forceinline__ void load_af0(uint2 af0[4], const float* __restrict__ x,
                                         int tile, int g, int tg) {
  #pragma unroll
  for (int i = 0; i < 4; i++) {
    uint32_t ax = 0, ay = 0;
    if (tg < 2) {
      int rp = tile * 64 + i * 16 + g;
      int im = rp >> 18, h = rp & (HW_ - 1);
      const float* xq = x + (size_t)im * 3 * HW_ + h;
      float va  = (tg == 0) ? __ldg(xq)            : __ldg(xq + 2 * (size_t)HW_);
      float vb  = (tg == 0) ? __ldg(xq + HW_)      : 0.f;
      float va2 = (tg == 0) ? __ldg(xq + 8)        : __ldg(xq + 2 * (size_t)HW_ + 8);
      float vb2 = (tg == 0) ? __ldg(xq + HW_ + 8)  : 0.f;
      ax = packh2(va, vb);
      ay = packh2(va2, vb2);
    }
    af0[i] = make_uint2(ax, ay);
  }
}
__device__ __forceinline__ void reduce_store(const float4* __restrict__ P, int tile,
                                             const float* __restrict__ x, float* __restrict__ out,
                                             int wid, int lane, int g, int tg) {
  float4 s = P[(wid * 8) * 32 + lane];
  #pragma unroll
  for (int k = 1; k < 8; k++) {
    float4 q = P[(wid * 8 + k) * 32 + lane];
    s.x += q.x; s.y += q.y; s.z += q.z; s.w += q.w;
  }
  int p = tile * 64 + wid * 16 + g;
  int img = p >> 18, hw = p & (HW_ - 1);
  const float* xb = x + (size_t)img * 3 * HW_ + hw;
  float* ob = out + (size_t)img * 3 * HW_ + hw;
  if (tg == 0) {
    float bb0 = __ldg(&g_b4f[0]), bb1 = __ldg(&g_b4f[1]);
    ob[0]       = clipf(__ldg(xb) + s.x + bb0);
    ob[HW_]     = clipf(__ldg(xb + HW_) + s.y + bb1);
    ob[8]       = clipf(__ldg(xb + 8) + s.z + bb0);
    ob[HW_ + 8] = clipf(__ldg(xb + HW_ + 8) + s.w + bb1);
  } else if (tg == 1) {
    float bb2 = __ldg(&g_b4f[2]);
    ob[2 * (size_t)HW_]     = clipf(__ldg(xb + 2 * (size_t)HW_) + s.x + bb2);
    ob[2 * (size_t)HW_ + 8] = clipf(__ldg(xb + 2 * (size_t)HW_ + 8) + s.z + bb2);
  }
}

// ---------------- main: persistent, dual-stream pipelined, 256 thr, 1 CTA/SM ----------------
#define SMEM_TOTAL 98304

__global__ void __launch_bounds__(256, 1) cnilut_main(
    const float* __restrict__ x, float* __restrict__ out) {
  extern __shared__ char smem[];
  uint4* B0 = (uint4*)smem;
  uint4* B1 = (uint4*)(smem + 32768);
  uint4* B2 = (uint4*)(smem + 65536);

  int tid = threadIdx.x, wid = tid >> 5, lane = tid & 31;
  int g = lane >> 2, tg = lane & 3;

  float accX[4][4][4], accY[4][4][4];
  uint2 af0X[4], af0Y[4];

  int pair0 = blockIdx.x;
  load_af0(af0X, x, 2 * pair0, g, tg);
  load_af0(af0Y, x, 2 * pair0 + 1, g, tg);

  #pragma unroll 1
  for (int pair = pair0; pair < NPAIRS; pair += GRIDP) {
    int tX = 2 * pair, tY = 2 * pair + 1;

    // ---- prologue: X.L0 -> B0; bias accY(c0) ----
    bias_from(accX, g_c0f, wid, tg);
    l0_mma(accX, af0X, wid, lane);
    epi_standalone<0>(accX, B0, nullptr, wid, lane);
    bias_from(accY, g_c0f, wid, tg);
    __syncthreads();

    // ---- P1: X.H1 (B0) || Y.L0 MMA + relu frags -> B1 ----
    bias_from(accX, g_bsf, wid, tg);
    l0_mma(accY, af0Y, wid, lane);
    phase<0>(accX, B0, g_bf[0], accY, B1, nullptr, wid, lane, tg);
    __syncthreads();

    // ---- P2: Y.H1 (B1) || X.H1-epi tanh -> B2 ----
    bias_from(accY, g_bsf, wid, tg);
    phase<1>(accY, B1, g_bf[0], accX, B2, nullptr, wid, lane, tg);
    __syncthreads();

    // ---- P3: X.H2 (B2) || Y.H1-epi tanh -> B0 ----
    bias_from(accX, g_bsf + 64, wid, tg);
    phase<1>(accX, B2, g_bf[1], accY, B0, nullptr, wid, lane, tg);
    __syncthreads();

    // ---- P4: Y.H2 (B0) || X.H2-epi tanh -> B1 ----
    bias_from(accY, g_bsf + 64, wid, tg);
    phase<1>(accY, B0, g_bf[1], accX, B1, nullptr, wid, lane, tg);
    __syncthreads();

    // ---- P5: X.H3 (B1) || Y.H2-epi tanh -> B2 ----
    bias_from(accX, g_bsf + 128, wid, tg);
    phase<1>(accX, B1, g_bf[2], accY, B2, nullptr, wid, lane, tg);
    __syncthreads();

    // ---- P6: Y.H3 (B2) || X.final (tanh + MMA into resX); partials -> B0 ----
    {
      float resX[4][4];
      bias_from(accY, g_bsf + 128, wid, tg);
      res_zero(resX);
      phase<2>(accY, B2, g_bf[2], accX, nullptr, resX, wid, lane, tg);
      float4* PX = (float4*)B0;
      #pragma unroll
      for (int i = 0; i < 4; i++)
        PX[(i * 8 + wid) * 32 + lane] = make_float4(resX[i][0], resX[i][1], resX[i][2], resX[i][3]);
    }
    __syncthreads();

    // ---- P7: Y.final standalone -> partials B1; X reduce+store; next-pair x prefetch ----
    if (pair + GRIDP < NPAIRS) {
      load_af0(af0X, x, 2 * (pair + GRIDP), g, tg);
      load_af0(af0Y, x, 2 * (pair + GRIDP) + 1, g, tg);
    }
    {
      float resY[4][4];
      res_zero(resY);
      epi_standalone<2>(accY, nullptr, resY, wid, lane);
      float4* PY = (float4*)B1;
      #pragma unroll
      for (int i = 0; i < 4; i++)
        PY[(i * 8 + wid) * 32 + lane] = make_float4(resY[i][0], resY[i][1], resY[i][2], resY[i][3]);
    }
    if (wid < 4) reduce_store((const float4*)B0, tX, x, out, wid, lane, g, tg);
    __syncthreads();

    // ---- P8: Y reduce+store ----
    if (wid < 4) reduce_store((const float4*)B1, tY, x, out, wid, lane, g, tg);
  }
}

extern "C" void kernel_launch(void* const* d_in, const int* in_sizes, int n_in,
                              void* d_out, int out_size) {
  const float* x     = (const float*)d_in[0];
  const float* style = (const float*)d_in[1];
  const float* W0    = (const float*)d_in[2];
  const float* b0    = (const float*)d_in[3];
  const float* W1    = (const float*)d_in[4];
  const float* b1    = (const float*)d_in[5];
  const float* W2    = (const float*)d_in[6];
  const float* b2    = (const float*)d_in[7];
  const float* W3    = (const float*)d_in[8];
  const float* b3    = (const float*)d_in[9];
  const float* W4    = (const float*)d_in[10];
  const float* b4    = (const float*)d_in[11];
  float* out = (float*)d_out;

  prep_kernel<<<794, 256>>>(W0, W1, W2, W3, W4, style, b0, b1, b2, b3, b4);
  cudaFuncSetAttribute(cnilut_main, cudaFuncAttributeMaxDynamicSharedMemorySize, SMEM_TOTAL);
  cnilut_main<<<GRIDP, 256, SMEM_TOTAL>>>(x, out);
}

// round 12
// speedup vs baseline: 1.2909x; 1.0418x over previous
#include <cuda_runtime.h>
#include <cuda_fp16.h>
#include <cstdint>

#define HW_ 262144            // 512*512
#define TILE 64
#define GRID 16384

// Fragment-linear fp16 weight images for mma.sync m16n8k16 B operand.
__device__ __align__(16) __half g_bf[3][65536];  // W1..W3 [kb(16)][n8pair(16)][lane(32)][8]
__device__ __align__(16) __half g_w0f[4096];     // W0 [1 kb][n8pair(16)][lane(32)][8], k<3 live
__device__ __align__(16) __half g_w4f[2048];     // W4 [kb(16)][lane(32)][2 x f16x2]
__device__ __align__(16) float4 g_c0f[64];       // layer0 bias frags [wid*4+jj(16)][tg(4)]
__device__ __align__(16) float4 g_bsf[192];      // [l(3)][16][tg(4)]
__device__ float g_b4f[4];

// ---------------- prep: fp32 W -> fp16 fragment-linear + packed biases ----------------
__global__ void prep_kernel(const float* __restrict__ W0, const float* __restrict__ W1,
                            const float* __restrict__ W2, const float* __restrict__ W3,
                            const float* __restrict__ W4, const float* __restrict__ style,
                            const float* __restrict__ b0, const float* __restrict__ b1,
                            const float* __restrict__ b2, const float* __restrict__ b3,
                            const float* __restrict__ b4) {
  int t = blockIdx.x * blockDim.x + threadIdx.x;
  if (t < 196608) {
    int l = t >> 16, e = t & 65535;
    int k = e >> 8, n = e & 255;
    const float* W = (l == 0) ? W1 : (l == 1 ? W2 : W3);
    int kb = k >> 4, kr = k & 15;
    int n8 = n >> 3, g = n & 7;
    int tg = (kr >> 1) & 3;
    int lane = g * 4 + tg;
    int breg = kr >> 3, hs = kr & 1;
    int halfidx = (n8 & 1) * 4 + breg * 2 + hs;
    int dst = ((kb * 16 + (n8 >> 1)) * 32 + lane) * 8 + halfidx;
    g_bf[l][dst] = __float2half_rn(W[k * 256 + n]);
  } else if (t < 200704) {
    int e = t - 196608;                  // k(16) x n(256)
    int k = e >> 8, n = e & 255;
    int n8 = n >> 3, g = n & 7;
    int tg = (k >> 1) & 3;
    int lane = g * 4 + tg;
    int breg = k >> 3, hs = k & 1;
    int halfidx = (n8 & 1) * 4 + breg * 2 + hs;
    int dst = ((n8 >> 1) * 32 + lane) * 8 + halfidx;
    g_w0f[dst] = __float2half_rn(k < 3 ? W0[k * 256 + n] : 0.f);
  } else if (t < 202752) {
    int e = t - 200704;                  // kglob(256) x n(8)
    int kglob = e >> 3, n = e & 7;
    int kbG = kglob >> 4, kr = kglob & 15;
    int tg = (kr >> 1) & 3;
    int lane = n * 4 + tg;
    int breg = kr >> 3, hs = kr & 1;
    int dst = ((kbG * 32 + lane) * 2 + breg) * 2 + hs;
    g_w4f[dst] = __float2half_rn(n < 3 ? W4[kglob * 3 + n] : 0.f);
  } else if (t < 202816) {
    int e = t - 202752;                  // layer0 bias frag: jj(16) tg(4)
    int jj = e >> 2, tg = e & 3;
    int c = jj * 16 + tg * 2;
    float s0 = style[0], s1 = style[1], s2 = style[2];
    float4 v;
    v.x = b0[c]     + s0 * W0[768 + c]     + s1 * W0[1024 + c]     + s2 * W0[1280 + c];
    v.y = b0[c + 1] + s0 * W0[768 + c + 1] + s1 * W0[1024 + c + 1] + s2 * W0[1280 + c + 1];
    v.z = b0[c + 8] + s0 * W0[768 + c + 8] + s1 * W0[1024 + c + 8] + s2 * W0[1280 + c + 8];
    v.w = b0[c + 9] + s0 * W0[768 + c + 9] + s1 * W0[1024 + c + 9] + s2 * W0[1280 + c + 9];
    g_c0f[e] = v;
  } else if (t < 203008) {
    int e = t - 202816;                  // hidden bias frag: l(3) jj(16) tg(4)
    int l = e >> 6, r = e & 63;
    int jj = r >> 2, tg = r & 3;
    int c = jj * 16 + tg * 2;
    const float* B = (l == 0) ? b1 : (l == 1 ? b2 : b3);
    g_bsf[e] = make_float4(B[c], B[c + 1], B[c + 8], B[c + 9]);
  } else if (t < 203012) {
    int e = t - 203008;
    g_b4f[e] = (e < 3) ? b4[e] : 0.f;
  }
}

// ---------------- helpers ----------------
__device__ __forceinline__ uint32_t packh2(float lo, float hi) {
  uint32_t r;
  asm("cvt.rn.f16x2.f32 %0, %1, %2;" : "=f"(*(float*)&r) : "f"(hi), "f"(lo));
  return r;
}
__device__ __forceinline__ uint32_t tanh2(uint32_t p) {
  uint32_t r;
  asm("tanh.approx.f16x2 %0, %1;" : "=r"(r) : "r"(p));
  return r;
}
__device__ __forceinline__ uint32_t max0h2(uint32_t p) {
  uint32_t r;
  asm("max.f16x2 %0, %1, %2;" : "=r"(r) : "r"(p), "r"(0u));
  return r;
}
__device__ __forceinline__ void mma16816(float* c, const uint4& a, uint32_t b0, uint32_t b1) {
  asm volatile("mma.sync.aligned.m16n8k16.row.col.f32.f16.f16.f32 "
               "{%0,%1,%2,%3}, {%4,%5,%6,%7}, {%8,%9}, {%0,%1,%2,%3};"
               : "+f"(c[0]), "+f"(c[1]), "+f"(c[2]), "+f"(c[3])
               : "r"(a.x), "r"(a.y), "r"(a.z), "r"(a.w), "r"(b0), "r"(b1));
}

// ---------------- main kernel: 128 thr, 2 CTAs/SM, single 32KB A buffer ----------------
__global__ void __launch_bounds__(128, 2) cnilut_main(
    const float* __restrict__ x, float* __restrict__ out) {
  __shared__ uint4 sA[2048];   // 32KB single buffer (also reused for final partials)

  int tid = threadIdx.x, wid = tid >> 5, lane = tid & 31;
  int g = lane >> 2, tg = lane & 3;

  // ---- early LDGs: layer0 B fragments + own pixels ----
  uint4 bf0[4];
  #pragma unroll
  for (int j = 0; j < 4; j++)
    bf0[j] = __ldg((const uint4*)g_w0f + (wid * 4 + j) * 32 + lane);

  int p0 = blockIdx.x * TILE + wid * 16 + g;
  int img = p0 >> 18, hw = p0 & (HW_ - 1);
  const float* xb = x + (size_t)img * 3 * HW_ + hw;
  float xv[2][3];
  #pragma unroll
  for (int c = 0; c < 3; c++) { xv[0][c] = xb[(size_t)c * HW_]; xv[1][c] = xb[(size_t)c * HW_ + 8]; }

  // layer0 A fragments from x (k = tg*2, tg*2+1; only k<3 live)
  uint4 af0[4];
  #pragma unroll
  for (int i = 0; i < 4; i++) {
    uint32_t ax = 0, ay = 0;
    if (tg < 2) {
      int rp = blockIdx.x * TILE + i * 16 + g;
      int im2 = rp >> 18, hw2 = rp & (HW_ - 1);
      const float* xq = x + (size_t)im2 * 3 * HW_ + hw2;
      float va  = (tg == 0) ? xq[0]        : xq[2 * (size_t)HW_];
      float vb  = (tg == 0) ? xq[HW_]      : 0.f;
      float va2 = (tg == 0) ? xq[8]        : xq[2 * (size_t)HW_ + 8];
      float vb2 = (tg == 0) ? xq[HW_ + 8]  : 0.f;
      ax = packh2(va, vb);
      ay = packh2(va2, vb2);
    }
    af0[i] = make_uint4(ax, ay, 0u, 0u);
  }

  float acc[4][8][4];

  // ---- layer 0 via MMA: relu(x.W0 + c0) -> sA ----
  {
    #pragma unroll
    for (int jj = 0; jj < 4; jj++) {
      float4 bv = __ldg(&g_c0f[(wid * 4 + jj) * 4 + tg]);
      #pragma unroll
      for (int i = 0; i < 4; i++) {
        acc[i][2 * jj][0] = bv.x; acc[i][2 * jj][1] = bv.y;
        acc[i][2 * jj][2] = bv.x; acc[i][2 * jj][3] = bv.y;
        acc[i][2 * jj + 1][0] = bv.z; acc[i][2 * jj + 1][1] = bv.w;
        acc[i][2 * jj + 1][2] = bv.z; acc[i][2 * jj + 1][3] = bv.w;
      }
    }
    #pragma unroll
    for (int i = 0; i < 4; i++)
      #pragma unroll
      for (int j = 0; j < 4; j++) {
        mma16816(acc[i][2 * j],     af0[i], bf0[j].x, bf0[j].y);
        mma16816(acc[i][2 * j + 1], af0[i], bf0[j].z, bf0[j].w);
      }
  }

  // prefetch first B fragments of hidden layer 0
  uint4 bfp0[4], bfp1[4];
  {
    const uint4* gB = (const uint4*)g_bf[0];
    #pragma unroll
    for (int j = 0; j < 4; j++) {
      bfp0[j] = __ldg(gB + (0 * 16 + wid * 4 + j) * 32 + lane);
      bfp1[j] = __ldg(gB + (1 * 16 + wid * 4 + j) * 32 + lane);
    }
  }

  // layer0 epilogue: relu + pack -> sA
  #pragma unroll
  for (int jj = 0; jj < 4; jj++) {
    #pragma unroll
    for (int i = 0; i < 4; i++) {
      float* e = acc[i][2 * jj];
      float* o = acc[i][2 * jj + 1];
      uint32_t a0 = max0h2(packh2(e[0], e[1]));
      uint32_t a1 = max0h2(packh2(e[2], e[3]));
      uint32_t a2 = max0h2(packh2(o[0], o[1]));
      uint32_t a3 = max0h2(packh2(o[2], o[3]));
      sA[(i * 16 + (wid * 4 + jj)) * 32 + lane] = make_uint4(a0, a1, a2, a3);
    }
  }
  __syncthreads();

  // ---- 3 hidden layers, single A buffer (2 barriers/layer) ----
  float res[4][4];
  uint2 wb[4];

  #pragma unroll 1
  for (int l = 0; l < 3; l++) {
    #pragma unroll
    for (int jj = 0; jj < 4; jj++) {
      float4 bv = __ldg(&g_bsf[l * 64 + (wid * 4 + jj) * 4 + tg]);
      #pragma unroll
      for (int i = 0; i < 4; i++) {
        acc[i][2 * jj][0] = bv.x; acc[i][2 * jj][1] = bv.y;
        acc[i][2 * jj][2] = bv.x; acc[i][2 * jj][3] = bv.y;
        acc[i][2 * jj + 1][0] = bv.z; acc[i][2 * jj + 1][1] = bv.w;
        acc[i][2 * jj + 1][2] = bv.z; acc[i][2 * jj + 1][3] = bv.w;
      }
    }

    const uint4* gB = (const uint4*)g_bf[l];
    uint4 bf[3][4];
    #pragma unroll
    for (int j = 0; j < 4; j++) { bf[0][j] = bfp0[j]; bf[1][j] = bfp1[j]; }

    #pragma unroll
    for (int kb = 0; kb < 16; kb++) {
      int cur = kb % 3;
      if (kb < 14) {
        int nxt = (kb + 2) % 3;
        #pragma unroll
        for (int j = 0; j < 4; j++)
          bf[nxt][j] = __ldg(gB + ((kb + 2) * 16 + wid * 4 + j) * 32 + lane);
      }
      uint4 af[4];
      #pragma unroll
      for (int i = 0; i < 4; i++) af[i] = sA[(i * 16 + kb) * 32 + lane];
      #pragma unroll
      for (int i = 0; i < 4; i++)
        #pragma unroll
        for (int j = 0; j < 4; j++) {
          mma16816(acc[i][2 * j],     af[i], bf[cur][j].x, bf[cur][j].y);
          mma16816(acc[i][2 * j + 1], af[i], bf[cur][j].z, bf[cur][j].w);
        }
    }

    if (l < 2) {
      // prefetch next layer's first B fragments before the barrier+epilogue
      const uint4* gBn = (const uint4*)g_bf[l + 1];
      #pragma unroll
      for (int j = 0; j < 4; j++) {
        bfp0[j] = __ldg(gBn + (0 * 16 + wid * 4 + j) * 32 + lane);
        bfp1[j] = __ldg(gBn + (1 * 16 + wid * 4 + j) * 32 + lane);
      }
      __syncthreads();   // all A reads of this layer done
      // epilogue: tanh + pack -> same buffer
      #pragma unroll
      for (int jj = 0; jj < 4; jj++) {
        #pragma unroll
        for (int i = 0; i < 4; i++) {
          float* e = acc[i][2 * jj];
          float* o = acc[i][2 * jj + 1];
          uint32_t a0 = tanh2(packh2(e[0], e[1]));
          uint32_t a1 = tanh2(packh2(e[2], e[3]));
          uint32_t a2 = tanh2(packh2(o[0], o[1]));
          uint32_t a3 = tanh2(packh2(o[2], o[3]));
          sA[(i * 16 + (wid * 4 + jj)) * 32 + lane] = make_uint4(a0, a1, a2, a3);
        }
      }
      __syncthreads();   // epilogue writes visible
    } else {
      // fused final: tanh-pack -> 16 HMMA (own k-slice) -> partials (regs only)
      #pragma unroll
      for (int jj = 0; jj < 4; jj++)
        wb[jj] = __ldg((const uint2*)g_w4f + (wid * 4 + jj) * 32 + lane);
      #pragma unroll
      for (int i = 0; i < 4; i++)
        #pragma unroll
        for (int r = 0; r < 4; r++) res[i][r] = 0.f;
      #pragma unroll
      for (int jj = 0; jj < 4; jj++) {
        #pragma unroll
        for (int i = 0; i < 4; i++) {
          float* e = acc[i][2 * jj];
          float* o = acc[i][2 * jj + 1];
          uint4 frag;
          frag.x = tanh2(packh2(e[0], e[1]));
          frag.y = tanh2(packh2(e[2], e[3]));
          frag.z = tanh2(packh2(o[0], o[1]));
          frag.w = tanh2(packh2(o[2], o[3]));
          mma16816(res[i], frag, wb[jj].x, wb[jj].y);
        }
      }
      __syncthreads();   // all A reads done before reusing sA for partials
      float4* P = (float4*)sA;
      #pragma unroll
      for (int i = 0; i < 4; i++)
        P[(wid * 4 + i) * 32 + lane] = make_float4(res[i][0], res[i][1], res[i][2], res[i][3]);
      __syncthreads();
    }
  }

  // ---- cross-warp reduce + residual + clip + store ----
  {
    const float4* P = (const float4*)sA;
    float4 q0 = P[(0 * 4 + wid) * 32 + lane];
    float4 q1 = P[(1 * 4 + wid) * 32 + lane];
    float4 q2 = P[(2 * 4 + wid) * 32 + lane];
    float4 q3 = P[(3 * 4 + wid) * 32 + lane];
    float r0 = q0.x + q1.x + q2.x + q3.x;   // pixel row g,   col tg*2
    float r1 = q0.y + q1.y + q2.y + q3.y;   // pixel row g,   col tg*2+1
    float r2 = q0.z + q1.z + q2.z + q3.z;   // pixel row g+8, col tg*2
    float r3 = q0.w + q1.w + q2.w + q3.w;   // pixel row g+8, col tg*2+1
    float* ob = out + (size_t)img * 3 * HW_ + hw;
    if (tg == 0) {
      float bb0 = __ldg(&g_b4f[0]), bb1 = __ldg(&g_b4f[1]);
      ob[0]        = fminf(fmaxf(xv[0][0] + r0 + bb0, 0.f), 1.f);
      ob[HW_]      = fminf(fmaxf(xv[0][1] + r1 + bb1, 0.f), 1.f);
      ob[8]        = fminf(fmaxf(xv[1][0] + r2 + bb0, 0.f), 1.f);
      ob[HW_ + 8]  = fminf(fmaxf(xv[1][1] + r3 + bb1, 0.f), 1.f);
    } else if (tg == 1) {
      float bb2 = __ldg(&g_b4f[2]);
      ob[2 * (size_t)HW_]     = fminf(fmaxf(xv[0][2] + r0 + bb2, 0.f), 1.f);
      ob[2 * (size_t)HW_ + 8] = fminf(fmaxf(xv[1][2] + r2 + bb2, 0.f), 1.f);
    }
  }
}

extern "C" void kernel_launch(void* const* d_in, const int* in_sizes, int n_in,
                              void* d_out, int out_size) {
  const float* x     = (const float*)d_in[0];
  const float* style = (const float*)d_in[1];
  const float* W0    = (const float*)d_in[2];
  const float* b0    = (const float*)d_in[3];
  const float* W1    = (const float*)d_in[4];
  const float* b1    = (const float*)d_in[5];
  const float* W2    = (const float*)d_in[6];
  const float* b2    = (const float*)d_in[7];
  const float* W3    = (const float*)d_in[8];
  const float* b3    = (const float*)d_in[9];
  const float* W4    = (const float*)d_in[10];
  const float* b4    = (const float*)d_in[11];
  float* out = (float*)d_out;

  prep_kernel<<<794, 256>>>(W0, W1, W2, W3, W4, style, b0, b1, b2, b3, b4);
  // Keep smem carveout small so the 128KB weight image stays L1-resident.
  cudaFuncSetAttribute(cnilut_main, cudaFuncAttributePreferredSharedMemoryCarveout, 29);
  cnilut_main<<<GRID, 128>>>(x, out);
}